// round 5
// baseline (speedup 1.0000x reference)
#include <cuda_runtime.h>
#include <cuda_bf16.h>
#include <mma.h>
#include <cstdint>

using namespace nvcuda;

#define NPIX 8192
#define NPTS 8192
#define NTOK 16384
#define NWIN 128
#define CAP  256
#define NCHUNK 32

// ---------------- scratch (device globals; no allocation) ----------------
__device__ __nv_bfloat16 g_feath[NTOK * 128], g_featl[NTOK * 128];
__device__ float g_qkv [NTOK * 384];
__device__ __nv_bfloat16 g_oh[NPIX * 128], g_ol[NPIX * 128];
__device__ float g_img [NPIX * 128];
__device__ __nv_bfloat16 g_resh[NPIX * 128], g_resl[NPIX * 128];
__device__ __nv_bfloat16 g_wh[147456];
__device__ __nv_bfloat16 g_wl[147456];
__device__ int   g_ptw [NPTS];
__device__ int   g_hist[NCHUNK * NWIN];
__device__ int   g_base[NCHUNK * NWIN];
__device__ int   g_win_tok[NWIN * CAP];
__device__ int   g_win_cnt[NWIN];

#define WOFF_CI  0
#define WOFF_QKV 32768
#define WOFF_PR  81920
#define WOFF_ODE 98304
#define WOFF_CO  114688

// ---------------- helpers ----------------
__device__ __forceinline__ uint32_t bf16x2_of(float hi, float lo) {
    uint32_t r; asm("cvt.rn.bf16x2.f32 %0, %1, %2;" : "=r"(r) : "f"(hi), "f"(lo)); return r;
}
__device__ __forceinline__ float bf16lo_f(uint32_t v) { return __uint_as_float(v << 16); }
__device__ __forceinline__ float bf16hi_f(uint32_t v) { return __uint_as_float(v & 0xffff0000u); }

__device__ __forceinline__ uint32_t smem_u32(const void* p) {
    uint32_t a;
    asm("{ .reg .u64 t; cvta.to.shared.u64 t, %1; cvt.u32.u64 %0, t; }" : "=r"(a) : "l"(p));
    return a;
}
__device__ __forceinline__ void cpa16(uint32_t s, const void* g) {
    asm volatile("cp.async.cg.shared.global [%0], [%1], 16;" :: "r"(s), "l"(g));
}
__device__ __forceinline__ void cp_commit() { asm volatile("cp.async.commit_group;" ::: "memory"); }
__device__ __forceinline__ void cp_wait1() { asm volatile("cp.async.wait_group 1;" ::: "memory"); }
__device__ __forceinline__ void cp_wait0() { asm volatile("cp.async.wait_group 0;" ::: "memory"); }

// ---------------- weight hi/lo split ----------------
__global__ void split_weights(const float* __restrict__ wci, const float* __restrict__ wqkv,
                              const float* __restrict__ wpr, const float* __restrict__ wode,
                              const float* __restrict__ wco) {
    int i = blockIdx.x * 256 + threadIdx.x;
    if (i >= 147456) return;
    float x;
    if (i < WOFF_QKV)      x = wci [i];
    else if (i < WOFF_PR)  x = wqkv[i - WOFF_QKV];
    else if (i < WOFF_ODE) x = wpr [i - WOFF_PR];
    else if (i < WOFF_CO)  x = wode[i - WOFF_ODE];
    else                   x = wco [i - WOFF_CO];
    __nv_bfloat16 h = __float2bfloat16(x);
    g_wh[i] = h;
    g_wl[i] = __float2bfloat16(x - __bfloat162float(h));
}

// ---------------- points feat split (replaces memcpy): rows 8192..16383 ----------------
__global__ void split_pts(const float* __restrict__ ptsf) {
    int i = blockIdx.x * 256 + threadIdx.x;   // over 262144 float4
    float4 v = ((const float4*)ptsf)[i];
    uint32_t h0 = bf16x2_of(v.y, v.x);
    uint32_t h1 = bf16x2_of(v.w, v.z);
    uint32_t l0 = bf16x2_of(v.y - bf16hi_f(h0), v.x - bf16lo_f(h0));
    uint32_t l1 = bf16x2_of(v.w - bf16hi_f(h1), v.z - bf16lo_f(h1));
    uint32_t* fh = (uint32_t*)g_feath;
    uint32_t* fl = (uint32_t*)g_featl;
    int o = 524288 + 2 * i;    // NPIX*128/2 + ...
    fh[o] = h0; fh[o + 1] = h1;
    fl[o] = l0; fl[o + 1] = l1;
}

// ============================================================================
// Window build (deterministic 3-pass)
// ============================================================================
__global__ void pt_wid_hist(const int* __restrict__ uv) {
    __shared__ int cnt[NWIN];
    int t = threadIdx.x;
    int i = blockIdx.x * 256 + t;
    if (t < NWIN) cnt[t] = 0;
    __syncthreads();
    int b = uv[3 * i] & 1;
    int u = uv[3 * i + 1] & 63;
    int v = uv[3 * i + 2] & 63;
    int wid = ((b * 8 + (v >> 3)) << 3) + (u >> 3);
    g_ptw[i] = wid;
    atomicAdd(&cnt[wid], 1);
    {
        int w = i >> 6, r = i & 63;
        int wb = w >> 6, wy = (w >> 3) & 7, wx = w & 7;
        int pv = wy * 8 + (r >> 3), pu = wx * 8 + (r & 7);
        g_win_tok[w * CAP + r] = wb * 4096 + pv * 64 + pu;
    }
    __syncthreads();
    if (t < NWIN) g_hist[blockIdx.x * NWIN + t] = cnt[t];
}

__global__ void win_scan() {
    int w = threadIdx.x;
    int run = 0;
#pragma unroll
    for (int c = 0; c < NCHUNK; c++) {
        g_base[c * NWIN + w] = run;
        run += g_hist[c * NWIN + w];
    }
    int tot = 64 + run;
    g_win_cnt[w] = tot < CAP ? tot : CAP;
}

__global__ void pt_scatter() {
    __shared__ int cnt[NWIN];
    int t = threadIdx.x;
    int lane = t & 31;
    int i = blockIdx.x * 256 + t;
    if (t < NWIN) cnt[t] = g_base[blockIdx.x * NWIN + t];
    __syncthreads();
    int wid = g_ptw[i];
    for (int wv = 0; wv < 8; wv++) {
        if ((t >> 5) == wv) {
            unsigned mask = __match_any_sync(0xffffffffu, wid);
            int prior = __popc(mask & ((1u << lane) - 1u));
            int base = cnt[wid];
            __syncwarp();
            int rank = 64 + base + prior;
            if (rank < CAP) g_win_tok[wid * CAP + rank] = NPIX + i;
            if (prior == 0) cnt[wid] = base + __popc(mask);
        }
        __syncthreads();
    }
}

// ============================================================================
// conv_in GEMM: A from NCHW fp32 (col_major frags), OUT = bf16 h/l feat.
// ============================================================================
__global__ __launch_bounds__(256) void bfgemm_ca(const float* __restrict__ img,
                                                 const __nv_bfloat16* __restrict__ Bh,
                                                 const __nv_bfloat16* __restrict__ Bl,
                                                 const float* __restrict__ bias,
                                                 __nv_bfloat16* __restrict__ Ch,
                                                 __nv_bfloat16* __restrict__ Cl, int N, int K) {
    __shared__ __align__(16) __nv_bfloat16 sAh[16 * 136], sAl[16 * 136];
    __shared__ __align__(16) __nv_bfloat16 sBh[64 * 16],  sBl[64 * 16];
    __shared__ __align__(16) float scratch[128 * 64];

    const int t = threadIdx.x;
    const int w = t >> 5;
    const int row0 = blockIdx.y << 7, col0 = blockIdx.x << 6;
    const int b = row0 >> 12, hw0 = row0 & 4095;
    const int wm = w >> 1, wn = w & 1;
    const int m0 = wm << 5, n0 = wn << 5;

    wmma::fragment<wmma::accumulator, 16, 16, 16, float> acc[2][2];
#pragma unroll
    for (int mi = 0; mi < 2; mi++)
#pragma unroll
        for (int ni = 0; ni < 2; ni++)
            wmma::fill_fragment(acc[mi][ni], 0.f);

    const uint32_t* Bh32 = (const uint32_t*)Bh;
    const uint32_t* Bl32 = (const uint32_t*)Bl;
    uint32_t* sBh32 = (uint32_t*)sBh;
    uint32_t* sBl32 = (uint32_t*)sBl;
    uint32_t* sAh32 = (uint32_t*)sAh;
    uint32_t* sAl32 = (uint32_t*)sAl;

    for (int k0 = 0; k0 < K; k0 += 16) {
#pragma unroll
        for (int i = 0; i < 2; i++) {
            int idx = t + (i << 8);
            int kk = idx >> 5, m4 = (idx & 31) << 2;
            float4 v = *(const float4*)(img + (size_t)b * 1048576 + (size_t)(k0 + kk) * 4096 + hw0 + m4);
            uint32_t h01 = bf16x2_of(v.y, v.x);
            uint32_t h23 = bf16x2_of(v.w, v.z);
            uint32_t l01 = bf16x2_of(v.y - bf16hi_f(h01), v.x - bf16lo_f(h01));
            uint32_t l23 = bf16x2_of(v.w - bf16hi_f(h23), v.z - bf16lo_f(h23));
            int so = kk * 68 + (m4 >> 1);
            sAh32[so] = h01; sAh32[so + 1] = h23;
            sAl32[so] = l01; sAl32[so + 1] = l23;
        }
#pragma unroll
        for (int i = 0; i < 2; i++) {
            int idx = t + (i << 8);
            int r = idx >> 3, c2 = idx & 7;
            size_t g = (size_t)(col0 + r) * (K >> 1) + (k0 >> 1) + c2;
            sBh32[(r << 3) + c2] = Bh32[g];
            sBl32[(r << 3) + c2] = Bl32[g];
        }
        __syncthreads();

        wmma::fragment<wmma::matrix_a, 16, 16, 16, __nv_bfloat16, wmma::col_major> ah0, ah1, al0, al1;
        wmma::fragment<wmma::matrix_b, 16, 16, 16, __nv_bfloat16, wmma::col_major> bh0, bh1, bl0, bl1;
        wmma::load_matrix_sync(ah0, sAh + m0, 136);
        wmma::load_matrix_sync(ah1, sAh + m0 + 16, 136);
        wmma::load_matrix_sync(al0, sAl + m0, 136);
        wmma::load_matrix_sync(al1, sAl + m0 + 16, 136);
        wmma::load_matrix_sync(bh0, sBh + (size_t)n0 * 16, 16);
        wmma::load_matrix_sync(bh1, sBh + (size_t)(n0 + 16) * 16, 16);
        wmma::load_matrix_sync(bl0, sBl + (size_t)n0 * 16, 16);
        wmma::load_matrix_sync(bl1, sBl + (size_t)(n0 + 16) * 16, 16);

        wmma::mma_sync(acc[0][0], ah0, bh0, acc[0][0]);
        wmma::mma_sync(acc[0][1], ah0, bh1, acc[0][1]);
        wmma::mma_sync(acc[1][0], ah1, bh0, acc[1][0]);
        wmma::mma_sync(acc[1][1], ah1, bh1, acc[1][1]);
        wmma::mma_sync(acc[0][0], ah0, bl0, acc[0][0]);
        wmma::mma_sync(acc[0][1], ah0, bl1, acc[0][1]);
        wmma::mma_sync(acc[1][0], ah1, bl0, acc[1][0]);
        wmma::mma_sync(acc[1][1], ah1, bl1, acc[1][1]);
        wmma::mma_sync(acc[0][0], al0, bh0, acc[0][0]);
        wmma::mma_sync(acc[0][1], al0, bh1, acc[0][1]);
        wmma::mma_sync(acc[1][0], al1, bh0, acc[1][0]);
        wmma::mma_sync(acc[1][1], al1, bh1, acc[1][1]);
        __syncthreads();
    }

#pragma unroll
    for (int mi = 0; mi < 2; mi++)
#pragma unroll
        for (int ni = 0; ni < 2; ni++)
            wmma::store_matrix_sync(scratch + (size_t)(m0 + mi * 16) * 64 + n0 + ni * 16,
                                    acc[mi][ni], 64, wmma::mem_row_major);
    __syncthreads();

    // epilogue: bias + split to bf16 h/l
    int r = t >> 1, cc = (t & 1) << 5;
    uint32_t* ch32 = (uint32_t*)Ch;
    uint32_t* cl32 = (uint32_t*)Cl;
#pragma unroll
    for (int q = 0; q < 8; q++) {
        float4 v = *(float4*)(scratch + r * 64 + cc + q * 4);
        float4 bb = *(const float4*)(bias + col0 + cc + q * 4);
        v.x += bb.x; v.y += bb.y; v.z += bb.z; v.w += bb.w;
        uint32_t h01 = bf16x2_of(v.y, v.x);
        uint32_t h23 = bf16x2_of(v.w, v.z);
        uint32_t l01 = bf16x2_of(v.y - bf16hi_f(h01), v.x - bf16lo_f(h01));
        uint32_t l23 = bf16x2_of(v.w - bf16hi_f(h23), v.z - bf16lo_f(h23));
        int o = (row0 + r) * (N >> 1) + ((col0 + cc) >> 1) + q * 2;
        ch32[o] = h01; ch32[o + 1] = h23;
        cl32[o] = l01; cl32[o + 1] = l23;
    }
}

// ============================================================================
// Pipelined bf16 GEMM: C[M][ldc] (+col0) = A(h+l)[M][K] @ B(h+l)[N][K]^T + bias
// cp.async double-buffered, K-step 32, pitch 40 (anti-conflict).
// dyn smem: Ah0|Ah1|Al0|Al1 (10240 ea) Bh0|Bh1|Bl0|Bl1 (5120 ea) scratch 32768
// ============================================================================
#define GBF_SMEM (40960 + 20480 + 32768)

__global__ __launch_bounds__(256) void bfgemm_bf(const __nv_bfloat16* __restrict__ Ah,
                                                 const __nv_bfloat16* __restrict__ Al,
                                                 const __nv_bfloat16* __restrict__ Bh,
                                                 const __nv_bfloat16* __restrict__ Bl,
                                                 const float* __restrict__ bias,
                                                 float* __restrict__ C, int ldc, int K) {
    extern __shared__ __align__(16) char sm[];
    __nv_bfloat16* sA[4];  // Ah0, Ah1, Al0, Al1
    __nv_bfloat16* sB[4];
    uint32_t aA[4], aB[4];
#pragma unroll
    for (int i = 0; i < 4; i++) {
        sA[i] = (__nv_bfloat16*)(sm + i * 10240);
        sB[i] = (__nv_bfloat16*)(sm + 40960 + i * 5120);
        aA[i] = smem_u32(sA[i]);
        aB[i] = smem_u32(sB[i]);
    }
    float* scratch = (float*)(sm + 61440);

    const int t = threadIdx.x;
    const int w = t >> 5;
    const int row0 = blockIdx.y << 7, col0 = blockIdx.x << 6;
    const int wm = w >> 1, wn = w & 1;
    const int m0 = wm << 5, n0 = wn << 5;

    wmma::fragment<wmma::accumulator, 16, 16, 16, float> acc[2][2];
#pragma unroll
    for (int mi = 0; mi < 2; mi++)
#pragma unroll
        for (int ni = 0; ni < 2; ni++)
            wmma::fill_fragment(acc[mi][ni], 0.f);

    const int KT = K >> 5;
    // issue tile kt into buffer b
    auto issue = [&](int kt, int b) {
        int k0 = kt << 5;
#pragma unroll
        for (int i = 0; i < 2; i++) {
            int id = t + (i << 8);
            int r = id >> 2, k8 = (id & 3) << 3;
            uint32_t so = (uint32_t)(r * 40 + k8) << 1;
            cpa16(aA[b] + so,     Ah + (size_t)(row0 + r) * K + k0 + k8);
            cpa16(aA[b + 2] + so, Al + (size_t)(row0 + r) * K + k0 + k8);
        }
        {
            int r = t >> 2, k8 = (t & 3) << 3;
            uint32_t so = (uint32_t)(r * 40 + k8) << 1;
            cpa16(aB[b] + so,     Bh + (size_t)(col0 + r) * K + k0 + k8);
            cpa16(aB[b + 2] + so, Bl + (size_t)(col0 + r) * K + k0 + k8);
        }
        cp_commit();
    };

    issue(0, 0);
    for (int kt = 0; kt < KT; kt++) {
        int b = kt & 1;
        if (kt + 1 < KT) { issue(kt + 1, (kt + 1) & 1); cp_wait1(); }
        else cp_wait0();
        __syncthreads();
#pragma unroll
        for (int ks = 0; ks < 2; ks++) {
            wmma::fragment<wmma::matrix_a, 16, 16, 16, __nv_bfloat16, wmma::row_major> ah0, ah1, al0, al1;
            wmma::fragment<wmma::matrix_b, 16, 16, 16, __nv_bfloat16, wmma::col_major> bh0, bh1, bl0, bl1;
            wmma::load_matrix_sync(ah0, sA[b]     + (size_t)m0 * 40 + ks * 16, 40);
            wmma::load_matrix_sync(ah1, sA[b]     + (size_t)(m0 + 16) * 40 + ks * 16, 40);
            wmma::load_matrix_sync(al0, sA[b + 2] + (size_t)m0 * 40 + ks * 16, 40);
            wmma::load_matrix_sync(al1, sA[b + 2] + (size_t)(m0 + 16) * 40 + ks * 16, 40);
            wmma::load_matrix_sync(bh0, sB[b]     + (size_t)n0 * 40 + ks * 16, 40);
            wmma::load_matrix_sync(bh1, sB[b]     + (size_t)(n0 + 16) * 40 + ks * 16, 40);
            wmma::load_matrix_sync(bl0, sB[b + 2] + (size_t)n0 * 40 + ks * 16, 40);
            wmma::load_matrix_sync(bl1, sB[b + 2] + (size_t)(n0 + 16) * 40 + ks * 16, 40);

            wmma::mma_sync(acc[0][0], ah0, bh0, acc[0][0]);
            wmma::mma_sync(acc[0][1], ah0, bh1, acc[0][1]);
            wmma::mma_sync(acc[1][0], ah1, bh0, acc[1][0]);
            wmma::mma_sync(acc[1][1], ah1, bh1, acc[1][1]);
            wmma::mma_sync(acc[0][0], ah0, bl0, acc[0][0]);
            wmma::mma_sync(acc[0][1], ah0, bl1, acc[0][1]);
            wmma::mma_sync(acc[1][0], ah1, bl0, acc[1][0]);
            wmma::mma_sync(acc[1][1], ah1, bl1, acc[1][1]);
            wmma::mma_sync(acc[0][0], al0, bh0, acc[0][0]);
            wmma::mma_sync(acc[0][1], al0, bh1, acc[0][1]);
            wmma::mma_sync(acc[1][0], al1, bh0, acc[1][0]);
            wmma::mma_sync(acc[1][1], al1, bh1, acc[1][1]);
        }
        __syncthreads();
    }

#pragma unroll
    for (int mi = 0; mi < 2; mi++)
#pragma unroll
        for (int ni = 0; ni < 2; ni++)
            wmma::store_matrix_sync(scratch + (size_t)(m0 + mi * 16) * 64 + n0 + ni * 16,
                                    acc[mi][ni], 64, wmma::mem_row_major);
    __syncthreads();

    int r = t >> 1, cc = (t & 1) << 5;
#pragma unroll
    for (int q = 0; q < 8; q++) {
        float4 v = *(float4*)(scratch + r * 64 + cc + q * 4);
        float4 bb = *(const float4*)(bias + col0 + cc + q * 4);
        v.x += bb.x; v.y += bb.y; v.z += bb.z; v.w += bb.w;
        *(float4*)(C + (size_t)(row0 + r) * ldc + col0 + cc + q * 4) = v;
    }
}

// ============================================================================
// conv_out: pipelined bf16 GEMM with transposed NCHW store.
// dyn smem: pipeline 61440 + scratch 64*132*4 = 33792 -> 95232
// ============================================================================
#define GTR_SMEM (61440 + 33792)

__global__ __launch_bounds__(256) void bfgemm_tr_bf(const __nv_bfloat16* __restrict__ Ah,
                                                    const __nv_bfloat16* __restrict__ Al,
                                                    const __nv_bfloat16* __restrict__ Bh,
                                                    const __nv_bfloat16* __restrict__ Bl,
                                                    const float* __restrict__ bias,
                                                    float* __restrict__ out, int K) {
    extern __shared__ __align__(16) char sm[];
    __nv_bfloat16* sA[4];
    __nv_bfloat16* sB[4];
    uint32_t aA[4], aB[4];
#pragma unroll
    for (int i = 0; i < 4; i++) {
        sA[i] = (__nv_bfloat16*)(sm + i * 10240);
        sB[i] = (__nv_bfloat16*)(sm + 40960 + i * 5120);
        aA[i] = smem_u32(sA[i]);
        aB[i] = smem_u32(sB[i]);
    }
    float* scratch = (float*)(sm + 61440);

    const int t = threadIdx.x;
    const int w = t >> 5;
    const int row0 = blockIdx.y << 7, col0 = blockIdx.x << 6;
    const int b2 = row0 >> 12, hw0 = row0 & 4095;
    const int wm = w >> 1, wn = w & 1;
    const int m0 = wm << 5, n0 = wn << 5;

    wmma::fragment<wmma::accumulator, 16, 16, 16, float> acc[2][2];
#pragma unroll
    for (int mi = 0; mi < 2; mi++)
#pragma unroll
        for (int ni = 0; ni < 2; ni++)
            wmma::fill_fragment(acc[mi][ni], 0.f);

    const int KT = K >> 5;
    auto issue = [&](int kt, int b) {
        int k0 = kt << 5;
#pragma unroll
        for (int i = 0; i < 2; i++) {
            int id = t + (i << 8);
            int r = id >> 2, k8 = (id & 3) << 3;
            uint32_t so = (uint32_t)(r * 40 + k8) << 1;
            cpa16(aA[b] + so,     Ah + (size_t)(row0 + r) * K + k0 + k8);
            cpa16(aA[b + 2] + so, Al + (size_t)(row0 + r) * K + k0 + k8);
        }
        {
            int r = t >> 2, k8 = (t & 3) << 3;
            uint32_t so = (uint32_t)(r * 40 + k8) << 1;
            cpa16(aB[b] + so,     Bh + (size_t)(col0 + r) * K + k0 + k8);
            cpa16(aB[b + 2] + so, Bl + (size_t)(col0 + r) * K + k0 + k8);
        }
        cp_commit();
    };

    issue(0, 0);
    for (int kt = 0; kt < KT; kt++) {
        int b = kt & 1;
        if (kt + 1 < KT) { issue(kt + 1, (kt + 1) & 1); cp_wait1(); }
        else cp_wait0();
        __syncthreads();
#pragma unroll
        for (int ks = 0; ks < 2; ks++) {
            wmma::fragment<wmma::matrix_a, 16, 16, 16, __nv_bfloat16, wmma::row_major> ah0, ah1, al0, al1;
            wmma::fragment<wmma::matrix_b, 16, 16, 16, __nv_bfloat16, wmma::col_major> bh0, bh1, bl0, bl1;
            wmma::load_matrix_sync(ah0, sA[b]     + (size_t)m0 * 40 + ks * 16, 40);
            wmma::load_matrix_sync(ah1, sA[b]     + (size_t)(m0 + 16) * 40 + ks * 16, 40);
            wmma::load_matrix_sync(al0, sA[b + 2] + (size_t)m0 * 40 + ks * 16, 40);
            wmma::load_matrix_sync(al1, sA[b + 2] + (size_t)(m0 + 16) * 40 + ks * 16, 40);
            wmma::load_matrix_sync(bh0, sB[b]     + (size_t)n0 * 40 + ks * 16, 40);
            wmma::load_matrix_sync(bh1, sB[b]     + (size_t)(n0 + 16) * 40 + ks * 16, 40);
            wmma::load_matrix_sync(bl0, sB[b + 2] + (size_t)n0 * 40 + ks * 16, 40);
            wmma::load_matrix_sync(bl1, sB[b + 2] + (size_t)(n0 + 16) * 40 + ks * 16, 40);

            wmma::mma_sync(acc[0][0], ah0, bh0, acc[0][0]);
            wmma::mma_sync(acc[0][1], ah0, bh1, acc[0][1]);
            wmma::mma_sync(acc[1][0], ah1, bh0, acc[1][0]);
            wmma::mma_sync(acc[1][1], ah1, bh1, acc[1][1]);
            wmma::mma_sync(acc[0][0], ah0, bl0, acc[0][0]);
            wmma::mma_sync(acc[0][1], ah0, bl1, acc[0][1]);
            wmma::mma_sync(acc[1][0], ah1, bl0, acc[1][0]);
            wmma::mma_sync(acc[1][1], ah1, bl1, acc[1][1]);
            wmma::mma_sync(acc[0][0], al0, bh0, acc[0][0]);
            wmma::mma_sync(acc[0][1], al0, bh1, acc[0][1]);
            wmma::mma_sync(acc[1][0], al1, bh0, acc[1][0]);
            wmma::mma_sync(acc[1][1], al1, bh1, acc[1][1]);
        }
        __syncthreads();
    }

#pragma unroll
    for (int mi = 0; mi < 2; mi++)
#pragma unroll
        for (int ni = 0; ni < 2; ni++)
            wmma::store_matrix_sync(scratch + (size_t)(n0 + ni * 16) * 132 + m0 + mi * 16,
                                    acc[mi][ni], 132, wmma::mem_col_major);
    __syncthreads();

    const int lane = t & 31;
#pragma unroll
    for (int nn = 0; nn < 8; nn++) {
        int n = (w << 3) + nn;
        float bv = bias[col0 + n];
        float* orow = out + (size_t)b2 * 1048576 + (size_t)(col0 + n) * 4096 + hw0;
#pragma unroll
        for (int it = 0; it < 4; it++) {
            int m = (it << 5) + lane;
            orow[m] = scratch[n * 132 + m] + bv;
        }
    }
}

// ---------------- windowed attention: fp32 in, bf16 h/l out ----------------
__global__ __launch_bounds__(64) void attn_kernel(const float* __restrict__ qkv,
                                                  __nv_bfloat16* __restrict__ Oh,
                                                  __nv_bfloat16* __restrict__ Ol) {
    const int h = blockIdx.x, w = blockIdx.y;
    __shared__ float4 sK[CAP][4];
    __shared__ float4 sV[CAP][4];
    const int t = threadIdx.x;
    const int T = g_win_cnt[w];
    const int* wt = &g_win_tok[w * CAP];
    for (int j = t; j < T; j += 64) {
        int tok = wt[j];
        const float4* kp = (const float4*)(qkv + (size_t)tok * 384 + 128 + h * 16);
        const float4* vp = (const float4*)(qkv + (size_t)tok * 384 + 256 + h * 16);
        sK[j][0] = kp[0]; sK[j][1] = kp[1]; sK[j][2] = kp[2]; sK[j][3] = kp[3];
        sV[j][0] = vp[0]; sV[j][1] = vp[1]; sV[j][2] = vp[2]; sV[j][3] = vp[3];
    }
    __syncthreads();
    int qtok = wt[t];
    const float4* qp = (const float4*)(qkv + (size_t)qtok * 384 + h * 16);
    float4 q0 = qp[0], q1 = qp[1], q2 = qp[2], q3 = qp[3];
    float m = -1e30f, l = 0.f;
    float4 o0 = {0,0,0,0}, o1 = {0,0,0,0}, o2 = {0,0,0,0}, o3 = {0,0,0,0};
    for (int j = 0; j < T; j++) {
        float4 k0 = sK[j][0], k1 = sK[j][1], k2 = sK[j][2], k3 = sK[j][3];
        float s = q0.x*k0.x + q0.y*k0.y + q0.z*k0.z + q0.w*k0.w
                + q1.x*k1.x + q1.y*k1.y + q1.z*k1.z + q1.w*k1.w
                + q2.x*k2.x + q2.y*k2.y + q2.z*k2.z + q2.w*k2.w
                + q3.x*k3.x + q3.y*k3.y + q3.z*k3.z + q3.w*k3.w;
        s *= 0.25f;
        float mn = fmaxf(m, s);
        float sc = __expf(m - mn);
        float p  = __expf(s - mn);
        l = l * sc + p;
        float4 v0 = sV[j][0], v1 = sV[j][1], v2 = sV[j][2], v3 = sV[j][3];
        o0.x = o0.x*sc + p*v0.x; o0.y = o0.y*sc + p*v0.y; o0.z = o0.z*sc + p*v0.z; o0.w = o0.w*sc + p*v0.w;
        o1.x = o1.x*sc + p*v1.x; o1.y = o1.y*sc + p*v1.y; o1.z = o1.z*sc + p*v1.z; o1.w = o1.w*sc + p*v1.w;
        o2.x = o2.x*sc + p*v2.x; o2.y = o2.y*sc + p*v2.y; o2.z = o2.z*sc + p*v2.z; o2.w = o2.w*sc + p*v2.w;
        o3.x = o3.x*sc + p*v3.x; o3.y = o3.y*sc + p*v3.y; o3.z = o3.z*sc + p*v3.z; o3.w = o3.w*sc + p*v3.w;
        m = mn;
    }
    float inv = 1.f / l;
    float ov[16] = { o0.x*inv, o0.y*inv, o0.z*inv, o0.w*inv,
                     o1.x*inv, o1.y*inv, o1.z*inv, o1.w*inv,
                     o2.x*inv, o2.y*inv, o2.z*inv, o2.w*inv,
                     o3.x*inv, o3.y*inv, o3.z*inv, o3.w*inv };
    uint32_t* oh32 = (uint32_t*)Oh;
    uint32_t* ol32 = (uint32_t*)Ol;
    int ob = qtok * 64 + h * 8;
#pragma unroll
    for (int j = 0; j < 8; j++) {
        uint32_t hh = bf16x2_of(ov[2*j+1], ov[2*j]);
        oh32[ob + j] = hh;
        ol32[ob + j] = bf16x2_of(ov[2*j+1] - bf16hi_f(hh), ov[2*j] - bf16lo_f(hh));
    }
}

// ============================================================================
// Fused RK4 ODE (wmma bf16 h/l) — final store emits res as bf16 h/l.
// ============================================================================
#define ODE_SMEM 137728

__global__ __launch_bounds__(256, 1) void ode_wmma(const float* __restrict__ img,
                                                   const __nv_bfloat16* __restrict__ Wh_g,
                                                   const __nv_bfloat16* __restrict__ Wl_g,
                                                   const float* __restrict__ bias,
                                                   __nv_bfloat16* __restrict__ Rh,
                                                   __nv_bfloat16* __restrict__ Rl) {
    extern __shared__ __align__(16) char sm[];
    float* scratch = (float*)sm;
    float* sBias   = (float*)(sm + 32768);
    __nv_bfloat16* sWh = (__nv_bfloat16*)(sm + 33280);
    __nv_bfloat16* sWl = (__nv_bfloat16*)(sm + 68096);
    __nv_bfloat16* sZh = (__nv_bfloat16*)(sm + 102912);
    __nv_bfloat16* sZl = (__nv_bfloat16*)(sm + 120320);

    const int t = threadIdx.x;
    const int w = t >> 5;
    const int row0 = blockIdx.x << 6;

    const uint32_t* wh32 = (const uint32_t*)Wh_g;
    const uint32_t* wl32 = (const uint32_t*)Wl_g;
    uint32_t* sWh32 = (uint32_t*)sWh;
    uint32_t* sWl32 = (uint32_t*)sWl;
    for (int idx = t; idx < 8192; idx += 256) {
        int n = idx >> 6, c2 = idx & 63;
        sWh32[n * 68 + c2] = wh32[idx];
        sWl32[n * 68 + c2] = wl32[idx];
    }
    if (t < 128) sBias[t] = bias[t];

    const int r = t >> 2, c0 = (t & 3) << 5;
    float y[32], accv[32];
#pragma unroll
    for (int q = 0; q < 8; q++) {
        float4 v = *(const float4*)(img + (size_t)(row0 + r) * 128 + c0 + q * 4);
        y[q*4] = v.x; y[q*4+1] = v.y; y[q*4+2] = v.z; y[q*4+3] = v.w;
    }
    uint32_t* zh32 = (uint32_t*)(sZh + r * 136 + c0);
    uint32_t* zl32 = (uint32_t*)(sZl + r * 136 + c0);
#pragma unroll
    for (int j = 0; j < 16; j++) {
        float x0 = y[2*j], x1 = y[2*j+1];
        uint32_t h = bf16x2_of(x1, x0);
        zh32[j] = h;
        zl32[j] = bf16x2_of(x1 - bf16hi_f(h), x0 - bf16lo_f(h));
    }
    __syncthreads();

    const int wm = w >> 2, wn = w & 3;
    const int m0 = wm << 5, n0 = wn << 5;

    for (int ev = 0; ev < 16; ev++) {
        wmma::fragment<wmma::accumulator, 16, 16, 16, float> acc[2][2];
#pragma unroll
        for (int mi = 0; mi < 2; mi++)
#pragma unroll
            for (int ni = 0; ni < 2; ni++)
                wmma::fill_fragment(acc[mi][ni], 0.f);

#pragma unroll
        for (int k = 0; k < 8; k++) {
            wmma::fragment<wmma::matrix_a, 16, 16, 16, __nv_bfloat16, wmma::row_major> ah0, ah1, al0, al1;
            wmma::fragment<wmma::matrix_b, 16, 16, 16, __nv_bfloat16, wmma::col_major> bh0, bh1, bl0, bl1;
            wmma::load_matrix_sync(ah0, sZh + (size_t)m0 * 136 + k * 16, 136);
            wmma::load_matrix_sync(ah1, sZh + (size_t)(m0 + 16) * 136 + k * 16, 136);
            wmma::load_matrix_sync(al0, sZl + (size_t)m0 * 136 + k * 16, 136);
            wmma::load_matrix_sync(al1, sZl + (size_t)(m0 + 16) * 136 + k * 16, 136);
            wmma::load_matrix_sync(bh0, sWh + (size_t)n0 * 136 + k * 16, 136);
            wmma::load_matrix_sync(bh1, sWh + (size_t)(n0 + 16) * 136 + k * 16, 136);
            wmma::load_matrix_sync(bl0, sWl + (size_t)n0 * 136 + k * 16, 136);
            wmma::load_matrix_sync(bl1, sWl + (size_t)(n0 + 16) * 136 + k * 16, 136);

            wmma::mma_sync(acc[0][0], ah0, bh0, acc[0][0]);
            wmma::mma_sync(acc[0][1], ah0, bh1, acc[0][1]);
            wmma::mma_sync(acc[1][0], ah1, bh0, acc[1][0]);
            wmma::mma_sync(acc[1][1], ah1, bh1, acc[1][1]);
            wmma::mma_sync(acc[0][0], ah0, bl0, acc[0][0]);
            wmma::mma_sync(acc[0][1], ah0, bl1, acc[0][1]);
            wmma::mma_sync(acc[1][0], ah1, bl0, acc[1][0]);
            wmma::mma_sync(acc[1][1], ah1, bl1, acc[1][1]);
            wmma::mma_sync(acc[0][0], al0, bh0, acc[0][0]);
            wmma::mma_sync(acc[0][1], al0, bh1, acc[0][1]);
            wmma::mma_sync(acc[1][0], al1, bh0, acc[1][0]);
            wmma::mma_sync(acc[1][1], al1, bh1, acc[1][1]);
        }
#pragma unroll
        for (int mi = 0; mi < 2; mi++)
#pragma unroll
            for (int ni = 0; ni < 2; ni++)
                wmma::store_matrix_sync(scratch + (size_t)(m0 + mi * 16) * 128 + n0 + ni * 16,
                                        acc[mi][ni], 128, wmma::mem_row_major);
        __syncthreads();

        const int st = ev & 3;
        const float zc = (st < 2) ? 0.125f : 0.25f;
        const float aw = (st == 1 || st == 2) ? 2.f : 1.f;
#pragma unroll
        for (int j = 0; j < 16; j++) {
            float k0f = fmaxf(scratch[r * 128 + c0 + 2*j]     + sBias[c0 + 2*j],     0.f);
            float k1f = fmaxf(scratch[r * 128 + c0 + 2*j + 1] + sBias[c0 + 2*j + 1], 0.f);
            float a0 = (st == 0) ? k0f : accv[2*j]     + aw * k0f;
            float a1 = (st == 0) ? k1f : accv[2*j + 1] + aw * k1f;
            accv[2*j] = a0; accv[2*j+1] = a1;
            float z0, z1;
            if (st < 3) { z0 = y[2*j] + zc * k0f; z1 = y[2*j+1] + zc * k1f; }
            else {
                y[2*j]   += (1.f / 24.f) * a0;
                y[2*j+1] += (1.f / 24.f) * a1;
                z0 = y[2*j]; z1 = y[2*j+1];
            }
            uint32_t h = bf16x2_of(z1, z0);
            zh32[j] = h;
            zl32[j] = bf16x2_of(z1 - bf16hi_f(h), z0 - bf16lo_f(h));
        }
        __syncthreads();
    }

    // res = y_final + img, emitted as bf16 h/l
    uint32_t* rh32 = (uint32_t*)Rh;
    uint32_t* rl32 = (uint32_t*)Rl;
    int ob = (row0 + r) * 64 + (c0 >> 1);
#pragma unroll
    for (int q = 0; q < 8; q++) {
        float4 v = *(const float4*)(img + (size_t)(row0 + r) * 128 + c0 + q * 4);
        float r0 = v.x + y[q*4],   r1 = v.y + y[q*4+1];
        float r2 = v.z + y[q*4+2], r3 = v.w + y[q*4+3];
        uint32_t h01 = bf16x2_of(r1, r0);
        uint32_t h23 = bf16x2_of(r3, r2);
        rh32[ob + q*2]     = h01;
        rh32[ob + q*2 + 1] = h23;
        rl32[ob + q*2]     = bf16x2_of(r1 - bf16hi_f(h01), r0 - bf16lo_f(h01));
        rl32[ob + q*2 + 1] = bf16x2_of(r3 - bf16hi_f(h23), r2 - bf16lo_f(h23));
    }
}

// ---------------- launch ----------------
extern "C" void kernel_launch(void* const* d_in, const int* in_sizes, int n_in,
                              void* d_out, int out_size) {
    const float* img   = (const float*)d_in[0];
    const int*   ptsuv = (const int*)  d_in[1];
    const float* ptsf  = (const float*)d_in[2];
    const float* wci   = (const float*)d_in[3];
    const float* bci   = (const float*)d_in[4];
    const float* wqkv  = (const float*)d_in[5];
    const float* bqkv  = (const float*)d_in[6];
    const float* wpr   = (const float*)d_in[7];
    const float* bpr   = (const float*)d_in[8];
    const float* wode  = (const float*)d_in[9];
    const float* bode  = (const float*)d_in[10];
    const float* wco   = (const float*)d_in[11];
    const float* bco   = (const float*)d_in[12];
    float* out = (float*)d_out;

    float *pqkv, *pimg;
    __nv_bfloat16 *pwh, *pwl, *pfh, *pfl, *poh, *pol, *prh, *prl;
    cudaGetSymbolAddress((void**)&pqkv, g_qkv);
    cudaGetSymbolAddress((void**)&pimg, g_img);
    cudaGetSymbolAddress((void**)&pwh,  g_wh);
    cudaGetSymbolAddress((void**)&pwl,  g_wl);
    cudaGetSymbolAddress((void**)&pfh,  g_feath);
    cudaGetSymbolAddress((void**)&pfl,  g_featl);
    cudaGetSymbolAddress((void**)&poh,  g_oh);
    cudaGetSymbolAddress((void**)&pol,  g_ol);
    cudaGetSymbolAddress((void**)&prh,  g_resh);
    cudaGetSymbolAddress((void**)&prl,  g_resl);

    cudaFuncSetAttribute(ode_wmma,    cudaFuncAttributeMaxDynamicSharedMemorySize, ODE_SMEM);
    cudaFuncSetAttribute(bfgemm_bf,   cudaFuncAttributeMaxDynamicSharedMemorySize, GBF_SMEM);
    cudaFuncSetAttribute(bfgemm_tr_bf, cudaFuncAttributeMaxDynamicSharedMemorySize, GTR_SMEM);

    split_weights<<<576, 256>>>(wci, wqkv, wpr, wode, wco);
    split_pts<<<1024, 256>>>(ptsf);

    pt_wid_hist<<<NCHUNK, 256>>>(ptsuv);
    win_scan<<<1, 128>>>();
    pt_scatter<<<NCHUNK, 256>>>();

    // conv_in from NCHW -> feat h/l
    bfgemm_ca<<<dim3(2, 64), 256>>>(img, pwh + WOFF_CI, pwl + WOFF_CI, bci, pfh, pfl, 128, 256);
    // qkv: Q pixels only, KV all tokens
    bfgemm_bf<<<dim3(2, 64), 256, GBF_SMEM>>>(pfh, pfl, pwh + WOFF_QKV, pwl + WOFF_QKV,
                                              bqkv, pqkv, 384, 128);
    bfgemm_bf<<<dim3(4, 128), 256, GBF_SMEM>>>(pfh, pfl, pwh + WOFF_QKV + 128 * 128,
                                               pwl + WOFF_QKV + 128 * 128,
                                               bqkv + 128, pqkv + 128, 384, 128);
    // attention -> o h/l
    attn_kernel<<<dim3(8, 128), 64>>>(pqkv, poh, pol);
    // proj -> img fp32
    bfgemm_bf<<<dim3(2, 64), 256, GBF_SMEM>>>(poh, pol, pwh + WOFF_PR, pwl + WOFF_PR,
                                              bpr, pimg, 128, 128);
    // fused RK4 ODE -> res h/l
    ode_wmma<<<128, 256, ODE_SMEM>>>(pimg, pwh + WOFF_ODE, pwl + WOFF_ODE, bode, prh, prl);
    // conv_out -> NCHW out
    bfgemm_tr_bf<<<dim3(4, 64), 256, GTR_SMEM>>>(prh, prl, pwh + WOFF_CO, pwl + WOFF_CO,
                                                 bco, out, 128);
}

// round 6
// speedup vs baseline: 1.0402x; 1.0402x over previous
#include <cuda_runtime.h>
#include <cuda_bf16.h>
#include <mma.h>
#include <cstdint>

using namespace nvcuda;

#define NPIX 8192
#define NPTS 8192
#define NTOK 16384
#define NWIN 128
#define CAP  256
#define NCHUNK 32

// ---------------- scratch (device globals; no allocation) ----------------
__device__ __nv_bfloat16 g_feath[NTOK * 128], g_featl[NTOK * 128];
__device__ float g_qkv [NTOK * 384];
__device__ __nv_bfloat16 g_oh[NPIX * 128], g_ol[NPIX * 128];
__device__ __nv_bfloat16 g_resh[NPIX * 128], g_resl[NPIX * 128];
__device__ __nv_bfloat16 g_wh[147456];
__device__ __nv_bfloat16 g_wl[147456];
__device__ int   g_ptw [NPTS];
__device__ int   g_hist[NCHUNK * NWIN];
__device__ int   g_win_tok[NWIN * CAP];
__device__ int   g_win_cnt[NWIN];

#define WOFF_CI  0
#define WOFF_QKV 32768
#define WOFF_PR  81920
#define WOFF_ODE 98304
#define WOFF_CO  114688

// ---------------- helpers ----------------
__device__ __forceinline__ uint32_t bf16x2_of(float hi, float lo) {
    uint32_t r; asm("cvt.rn.bf16x2.f32 %0, %1, %2;" : "=r"(r) : "f"(hi), "f"(lo)); return r;
}
__device__ __forceinline__ float bf16lo_f(uint32_t v) { return __uint_as_float(v << 16); }
__device__ __forceinline__ float bf16hi_f(uint32_t v) { return __uint_as_float(v & 0xffff0000u); }

__device__ __forceinline__ uint32_t smem_u32(const void* p) {
    uint32_t a;
    asm("{ .reg .u64 t; cvta.to.shared.u64 t, %1; cvt.u32.u64 %0, t; }" : "=r"(a) : "l"(p));
    return a;
}
__device__ __forceinline__ void cpa16(uint32_t s, const void* g) {
    asm volatile("cp.async.cg.shared.global [%0], [%1], 16;" :: "r"(s), "l"(g));
}
__device__ __forceinline__ void cp_commit() { asm volatile("cp.async.commit_group;" ::: "memory"); }
__device__ __forceinline__ void cp_wait1() { asm volatile("cp.async.wait_group 1;" ::: "memory"); }
__device__ __forceinline__ void cp_wait0() { asm volatile("cp.async.wait_group 0;" ::: "memory"); }

// ============================================================================
// Merged prep: weight split | points split | wid+hist+pixel slots
//   blocks [0,576): weights; [576,1600): pts; [1600,1632): hist
// ============================================================================
__global__ void prep(const float* __restrict__ wci, const float* __restrict__ wqkv,
                     const float* __restrict__ wpr, const float* __restrict__ wode,
                     const float* __restrict__ wco, const float* __restrict__ ptsf,
                     const int* __restrict__ uv) {
    __shared__ int cnt[NWIN];
    int bid = blockIdx.x, t = threadIdx.x;
    if (bid < 576) {
        int i = bid * 256 + t;
        if (i >= 147456) return;
        float x;
        if (i < WOFF_QKV)      x = wci [i];
        else if (i < WOFF_PR)  x = wqkv[i - WOFF_QKV];
        else if (i < WOFF_ODE) x = wpr [i - WOFF_PR];
        else if (i < WOFF_CO)  x = wode[i - WOFF_ODE];
        else                   x = wco [i - WOFF_CO];
        __nv_bfloat16 h = __float2bfloat16(x);
        g_wh[i] = h;
        g_wl[i] = __float2bfloat16(x - __bfloat162float(h));
    } else if (bid < 1600) {
        int i = (bid - 576) * 256 + t;   // over 262144 float4
        float4 v = ((const float4*)ptsf)[i];
        uint32_t h0 = bf16x2_of(v.y, v.x);
        uint32_t h1 = bf16x2_of(v.w, v.z);
        uint32_t l0 = bf16x2_of(v.y - bf16hi_f(h0), v.x - bf16lo_f(h0));
        uint32_t l1 = bf16x2_of(v.w - bf16hi_f(h1), v.z - bf16lo_f(h1));
        uint32_t* fh = (uint32_t*)g_feath;
        uint32_t* fl = (uint32_t*)g_featl;
        int o = 524288 + 2 * i;
        fh[o] = h0; fh[o + 1] = h1;
        fl[o] = l0; fl[o + 1] = l1;
    } else {
        int c = bid - 1600;
        int i = c * 256 + t;
        if (t < NWIN) cnt[t] = 0;
        __syncthreads();
        int b = uv[3 * i] & 1;
        int u = uv[3 * i + 1] & 63;
        int v = uv[3 * i + 2] & 63;
        int wid = ((b * 8 + (v >> 3)) << 3) + (u >> 3);
        g_ptw[i] = wid;
        atomicAdd(&cnt[wid], 1);
        {
            int w = i >> 6, r = i & 63;
            int wb = w >> 6, wy = (w >> 3) & 7, wx = w & 7;
            int pv = wy * 8 + (r >> 3), pu = wx * 8 + (r & 7);
            g_win_tok[w * CAP + r] = wb * 4096 + pv * 64 + pu;
        }
        __syncthreads();
        if (t < NWIN) g_hist[c * NWIN + t] = cnt[t];
    }
}

// ---------------- scatter with inline cross-chunk scan ----------------
__global__ void pt_scatter() {
    __shared__ int cnt[NWIN];
    int t = threadIdx.x;
    int lane = t & 31;
    int c = blockIdx.x;
    int i = c * 256 + t;
    if (t < NWIN) {
        int run = 0;
        for (int cc = 0; cc < c; cc++) run += g_hist[cc * NWIN + t];
        cnt[t] = run;
        if (c == NCHUNK - 1) {
            int tot = 64 + run + g_hist[(NCHUNK - 1) * NWIN + t];
            g_win_cnt[t] = tot < CAP ? tot : CAP;
        }
    }
    __syncthreads();
    int wid = g_ptw[i];
    for (int wv = 0; wv < 8; wv++) {
        if ((t >> 5) == wv) {
            unsigned mask = __match_any_sync(0xffffffffu, wid);
            int prior = __popc(mask & ((1u << lane) - 1u));
            int base = cnt[wid];
            __syncwarp();
            int rank = 64 + base + prior;
            if (rank < CAP) g_win_tok[wid * CAP + rank] = NPIX + i;
            if (prior == 0) cnt[wid] = base + __popc(mask);
        }
        __syncthreads();
    }
}

// ============================================================================
// conv_in GEMM: A from NCHW fp32 (col_major frags), OUT = bf16 h/l feat.
// ============================================================================
__global__ __launch_bounds__(256) void bfgemm_ca(const float* __restrict__ img,
                                                 const __nv_bfloat16* __restrict__ Bh,
                                                 const __nv_bfloat16* __restrict__ Bl,
                                                 const float* __restrict__ bias,
                                                 __nv_bfloat16* __restrict__ Ch,
                                                 __nv_bfloat16* __restrict__ Cl, int N, int K) {
    __shared__ __align__(16) __nv_bfloat16 sAh[16 * 136], sAl[16 * 136];
    __shared__ __align__(16) __nv_bfloat16 sBh[64 * 16],  sBl[64 * 16];
    __shared__ __align__(16) float scratch[128 * 64];

    const int t = threadIdx.x;
    const int w = t >> 5;
    const int row0 = blockIdx.y << 7, col0 = blockIdx.x << 6;
    const int b = row0 >> 12, hw0 = row0 & 4095;
    const int wm = w >> 1, wn = w & 1;
    const int m0 = wm << 5, n0 = wn << 5;

    wmma::fragment<wmma::accumulator, 16, 16, 16, float> acc[2][2];
#pragma unroll
    for (int mi = 0; mi < 2; mi++)
#pragma unroll
        for (int ni = 0; ni < 2; ni++)
            wmma::fill_fragment(acc[mi][ni], 0.f);

    const uint32_t* Bh32 = (const uint32_t*)Bh;
    const uint32_t* Bl32 = (const uint32_t*)Bl;
    uint32_t* sBh32 = (uint32_t*)sBh;
    uint32_t* sBl32 = (uint32_t*)sBl;
    uint32_t* sAh32 = (uint32_t*)sAh;
    uint32_t* sAl32 = (uint32_t*)sAl;

    for (int k0 = 0; k0 < K; k0 += 16) {
#pragma unroll
        for (int i = 0; i < 2; i++) {
            int idx = t + (i << 8);
            int kk = idx >> 5, m4 = (idx & 31) << 2;
            float4 v = *(const float4*)(img + (size_t)b * 1048576 + (size_t)(k0 + kk) * 4096 + hw0 + m4);
            uint32_t h01 = bf16x2_of(v.y, v.x);
            uint32_t h23 = bf16x2_of(v.w, v.z);
            uint32_t l01 = bf16x2_of(v.y - bf16hi_f(h01), v.x - bf16lo_f(h01));
            uint32_t l23 = bf16x2_of(v.w - bf16hi_f(h23), v.z - bf16lo_f(h23));
            int so = kk * 68 + (m4 >> 1);
            sAh32[so] = h01; sAh32[so + 1] = h23;
            sAl32[so] = l01; sAl32[so + 1] = l23;
        }
#pragma unroll
        for (int i = 0; i < 2; i++) {
            int idx = t + (i << 8);
            int r = idx >> 3, c2 = idx & 7;
            size_t g = (size_t)(col0 + r) * (K >> 1) + (k0 >> 1) + c2;
            sBh32[(r << 3) + c2] = Bh32[g];
            sBl32[(r << 3) + c2] = Bl32[g];
        }
        __syncthreads();

        wmma::fragment<wmma::matrix_a, 16, 16, 16, __nv_bfloat16, wmma::col_major> ah0, ah1, al0, al1;
        wmma::fragment<wmma::matrix_b, 16, 16, 16, __nv_bfloat16, wmma::col_major> bh0, bh1, bl0, bl1;
        wmma::load_matrix_sync(ah0, sAh + m0, 136);
        wmma::load_matrix_sync(ah1, sAh + m0 + 16, 136);
        wmma::load_matrix_sync(al0, sAl + m0, 136);
        wmma::load_matrix_sync(al1, sAl + m0 + 16, 136);
        wmma::load_matrix_sync(bh0, sBh + (size_t)n0 * 16, 16);
        wmma::load_matrix_sync(bh1, sBh + (size_t)(n0 + 16) * 16, 16);
        wmma::load_matrix_sync(bl0, sBl + (size_t)n0 * 16, 16);
        wmma::load_matrix_sync(bl1, sBl + (size_t)(n0 + 16) * 16, 16);

        wmma::mma_sync(acc[0][0], ah0, bh0, acc[0][0]);
        wmma::mma_sync(acc[0][1], ah0, bh1, acc[0][1]);
        wmma::mma_sync(acc[1][0], ah1, bh0, acc[1][0]);
        wmma::mma_sync(acc[1][1], ah1, bh1, acc[1][1]);
        wmma::mma_sync(acc[0][0], ah0, bl0, acc[0][0]);
        wmma::mma_sync(acc[0][1], ah0, bl1, acc[0][1]);
        wmma::mma_sync(acc[1][0], ah1, bl0, acc[1][0]);
        wmma::mma_sync(acc[1][1], ah1, bl1, acc[1][1]);
        wmma::mma_sync(acc[0][0], al0, bh0, acc[0][0]);
        wmma::mma_sync(acc[0][1], al0, bh1, acc[0][1]);
        wmma::mma_sync(acc[1][0], al1, bh0, acc[1][0]);
        wmma::mma_sync(acc[1][1], al1, bh1, acc[1][1]);
        __syncthreads();
    }

#pragma unroll
    for (int mi = 0; mi < 2; mi++)
#pragma unroll
        for (int ni = 0; ni < 2; ni++)
            wmma::store_matrix_sync(scratch + (size_t)(m0 + mi * 16) * 64 + n0 + ni * 16,
                                    acc[mi][ni], 64, wmma::mem_row_major);
    __syncthreads();

    int r = t >> 1, cc = (t & 1) << 5;
    uint32_t* ch32 = (uint32_t*)Ch;
    uint32_t* cl32 = (uint32_t*)Cl;
#pragma unroll
    for (int q = 0; q < 8; q++) {
        float4 v = *(float4*)(scratch + r * 64 + cc + q * 4);
        float4 bb = *(const float4*)(bias + col0 + cc + q * 4);
        v.x += bb.x; v.y += bb.y; v.z += bb.z; v.w += bb.w;
        uint32_t h01 = bf16x2_of(v.y, v.x);
        uint32_t h23 = bf16x2_of(v.w, v.z);
        uint32_t l01 = bf16x2_of(v.y - bf16hi_f(h01), v.x - bf16lo_f(h01));
        uint32_t l23 = bf16x2_of(v.w - bf16hi_f(h23), v.z - bf16lo_f(h23));
        int o = (row0 + r) * (N >> 1) + ((col0 + cc) >> 1) + q * 2;
        ch32[o] = h01; ch32[o + 1] = h23;
        cl32[o] = l01; cl32[o + 1] = l23;
    }
}

// ============================================================================
// Pipelined bf16 GEMM (scratch aliases cp.async buffers -> 60KB smem, 2 CTA/SM)
//   optional Q-split: skip blocks with col0 < qcolsplit && blockIdx.y >= qrowblk
// ============================================================================
#define GBF_SMEM 61440

__global__ __launch_bounds__(256) void bfgemm_bf(const __nv_bfloat16* __restrict__ Ah,
                                                 const __nv_bfloat16* __restrict__ Al,
                                                 const __nv_bfloat16* __restrict__ Bh,
                                                 const __nv_bfloat16* __restrict__ Bl,
                                                 const float* __restrict__ bias,
                                                 float* __restrict__ C, int ldc, int K,
                                                 int qcolsplit, int qrowblk) {
    extern __shared__ __align__(16) char sm[];
    const int col0 = blockIdx.x << 6;
    if (col0 < qcolsplit && (int)blockIdx.y >= qrowblk) return;

    __nv_bfloat16* sA[4];
    __nv_bfloat16* sB[4];
    uint32_t aA[4], aB[4];
#pragma unroll
    for (int i = 0; i < 4; i++) {
        sA[i] = (__nv_bfloat16*)(sm + i * 10240);
        sB[i] = (__nv_bfloat16*)(sm + 40960 + i * 5120);
        aA[i] = smem_u32(sA[i]);
        aB[i] = smem_u32(sB[i]);
    }
    float* scratch = (float*)sm;   // aliases sA buffers (used only after k-loop)

    const int t = threadIdx.x;
    const int w = t >> 5;
    const int row0 = blockIdx.y << 7;
    const int wm = w >> 1, wn = w & 1;
    const int m0 = wm << 5, n0 = wn << 5;

    wmma::fragment<wmma::accumulator, 16, 16, 16, float> acc[2][2];
#pragma unroll
    for (int mi = 0; mi < 2; mi++)
#pragma unroll
        for (int ni = 0; ni < 2; ni++)
            wmma::fill_fragment(acc[mi][ni], 0.f);

    const int KT = K >> 5;
    auto issue = [&](int kt, int b) {
        int k0 = kt << 5;
#pragma unroll
        for (int i = 0; i < 2; i++) {
            int id = t + (i << 8);
            int r = id >> 2, k8 = (id & 3) << 3;
            uint32_t so = (uint32_t)(r * 40 + k8) << 1;
            cpa16(aA[b] + so,     Ah + (size_t)(row0 + r) * K + k0 + k8);
            cpa16(aA[b + 2] + so, Al + (size_t)(row0 + r) * K + k0 + k8);
        }
        {
            int r = t >> 2, k8 = (t & 3) << 3;
            uint32_t so = (uint32_t)(r * 40 + k8) << 1;
            cpa16(aB[b] + so,     Bh + (size_t)(col0 + r) * K + k0 + k8);
            cpa16(aB[b + 2] + so, Bl + (size_t)(col0 + r) * K + k0 + k8);
        }
        cp_commit();
    };

    issue(0, 0);
    for (int kt = 0; kt < KT; kt++) {
        int b = kt & 1;
        if (kt + 1 < KT) { issue(kt + 1, (kt + 1) & 1); cp_wait1(); }
        else cp_wait0();
        __syncthreads();
#pragma unroll
        for (int ks = 0; ks < 2; ks++) {
            wmma::fragment<wmma::matrix_a, 16, 16, 16, __nv_bfloat16, wmma::row_major> ah0, ah1, al0, al1;
            wmma::fragment<wmma::matrix_b, 16, 16, 16, __nv_bfloat16, wmma::col_major> bh0, bh1, bl0, bl1;
            wmma::load_matrix_sync(ah0, sA[b]     + (size_t)m0 * 40 + ks * 16, 40);
            wmma::load_matrix_sync(ah1, sA[b]     + (size_t)(m0 + 16) * 40 + ks * 16, 40);
            wmma::load_matrix_sync(al0, sA[b + 2] + (size_t)m0 * 40 + ks * 16, 40);
            wmma::load_matrix_sync(al1, sA[b + 2] + (size_t)(m0 + 16) * 40 + ks * 16, 40);
            wmma::load_matrix_sync(bh0, sB[b]     + (size_t)n0 * 40 + ks * 16, 40);
            wmma::load_matrix_sync(bh1, sB[b]     + (size_t)(n0 + 16) * 40 + ks * 16, 40);
            wmma::load_matrix_sync(bl0, sB[b + 2] + (size_t)n0 * 40 + ks * 16, 40);
            wmma::load_matrix_sync(bl1, sB[b + 2] + (size_t)(n0 + 16) * 40 + ks * 16, 40);

            wmma::mma_sync(acc[0][0], ah0, bh0, acc[0][0]);
            wmma::mma_sync(acc[0][1], ah0, bh1, acc[0][1]);
            wmma::mma_sync(acc[1][0], ah1, bh0, acc[1][0]);
            wmma::mma_sync(acc[1][1], ah1, bh1, acc[1][1]);
            wmma::mma_sync(acc[0][0], ah0, bl0, acc[0][0]);
            wmma::mma_sync(acc[0][1], ah0, bl1, acc[0][1]);
            wmma::mma_sync(acc[1][0], ah1, bl0, acc[1][0]);
            wmma::mma_sync(acc[1][1], ah1, bl1, acc[1][1]);
            wmma::mma_sync(acc[0][0], al0, bh0, acc[0][0]);
            wmma::mma_sync(acc[0][1], al0, bh1, acc[0][1]);
            wmma::mma_sync(acc[1][0], al1, bh0, acc[1][0]);
            wmma::mma_sync(acc[1][1], al1, bh1, acc[1][1]);
        }
        __syncthreads();
    }

#pragma unroll
    for (int mi = 0; mi < 2; mi++)
#pragma unroll
        for (int ni = 0; ni < 2; ni++)
            wmma::store_matrix_sync(scratch + (size_t)(m0 + mi * 16) * 64 + n0 + ni * 16,
                                    acc[mi][ni], 64, wmma::mem_row_major);
    __syncthreads();

    int r = t >> 1, cc = (t & 1) << 5;
#pragma unroll
    for (int q = 0; q < 8; q++) {
        float4 v = *(float4*)(scratch + r * 64 + cc + q * 4);
        float4 bb = *(const float4*)(bias + col0 + cc + q * 4);
        v.x += bb.x; v.y += bb.y; v.z += bb.z; v.w += bb.w;
        *(float4*)(C + (size_t)(row0 + r) * ldc + col0 + cc + q * 4) = v;
    }
}

// ============================================================================
// conv_out: pipelined bf16 GEMM with transposed NCHW store (scratch aliased).
// ============================================================================
#define GTR_SMEM 61440

__global__ __launch_bounds__(256) void bfgemm_tr_bf(const __nv_bfloat16* __restrict__ Ah,
                                                    const __nv_bfloat16* __restrict__ Al,
                                                    const __nv_bfloat16* __restrict__ Bh,
                                                    const __nv_bfloat16* __restrict__ Bl,
                                                    const float* __restrict__ bias,
                                                    float* __restrict__ out, int K) {
    extern __shared__ __align__(16) char sm[];
    __nv_bfloat16* sA[4];
    __nv_bfloat16* sB[4];
    uint32_t aA[4], aB[4];
#pragma unroll
    for (int i = 0; i < 4; i++) {
        sA[i] = (__nv_bfloat16*)(sm + i * 10240);
        sB[i] = (__nv_bfloat16*)(sm + 40960 + i * 5120);
        aA[i] = smem_u32(sA[i]);
        aB[i] = smem_u32(sB[i]);
    }
    float* scratch = (float*)sm;   // 64*132*4 = 33792 <= 40960, aliases sA

    const int t = threadIdx.x;
    const int w = t >> 5;
    const int row0 = blockIdx.y << 7, col0 = blockIdx.x << 6;
    const int b2 = row0 >> 12, hw0 = row0 & 4095;
    const int wm = w >> 1, wn = w & 1;
    const int m0 = wm << 5, n0 = wn << 5;

    wmma::fragment<wmma::accumulator, 16, 16, 16, float> acc[2][2];
#pragma unroll
    for (int mi = 0; mi < 2; mi++)
#pragma unroll
        for (int ni = 0; ni < 2; ni++)
            wmma::fill_fragment(acc[mi][ni], 0.f);

    const int KT = K >> 5;
    auto issue = [&](int kt, int b) {
        int k0 = kt << 5;
#pragma unroll
        for (int i = 0; i < 2; i++) {
            int id = t + (i << 8);
            int r = id >> 2, k8 = (id & 3) << 3;
            uint32_t so = (uint32_t)(r * 40 + k8) << 1;
            cpa16(aA[b] + so,     Ah + (size_t)(row0 + r) * K + k0 + k8);
            cpa16(aA[b + 2] + so, Al + (size_t)(row0 + r) * K + k0 + k8);
        }
        {
            int r = t >> 2, k8 = (t & 3) << 3;
            uint32_t so = (uint32_t)(r * 40 + k8) << 1;
            cpa16(aB[b] + so,     Bh + (size_t)(col0 + r) * K + k0 + k8);
            cpa16(aB[b + 2] + so, Bl + (size_t)(col0 + r) * K + k0 + k8);
        }
        cp_commit();
    };

    issue(0, 0);
    for (int kt = 0; kt < KT; kt++) {
        int b = kt & 1;
        if (kt + 1 < KT) { issue(kt + 1, (kt + 1) & 1); cp_wait1(); }
        else cp_wait0();
        __syncthreads();
#pragma unroll
        for (int ks = 0; ks < 2; ks++) {
            wmma::fragment<wmma::matrix_a, 16, 16, 16, __nv_bfloat16, wmma::row_major> ah0, ah1, al0, al1;
            wmma::fragment<wmma::matrix_b, 16, 16, 16, __nv_bfloat16, wmma::col_major> bh0, bh1, bl0, bl1;
            wmma::load_matrix_sync(ah0, sA[b]     + (size_t)m0 * 40 + ks * 16, 40);
            wmma::load_matrix_sync(ah1, sA[b]     + (size_t)(m0 + 16) * 40 + ks * 16, 40);
            wmma::load_matrix_sync(al0, sA[b + 2] + (size_t)m0 * 40 + ks * 16, 40);
            wmma::load_matrix_sync(al1, sA[b + 2] + (size_t)(m0 + 16) * 40 + ks * 16, 40);
            wmma::load_matrix_sync(bh0, sB[b]     + (size_t)n0 * 40 + ks * 16, 40);
            wmma::load_matrix_sync(bh1, sB[b]     + (size_t)(n0 + 16) * 40 + ks * 16, 40);
            wmma::load_matrix_sync(bl0, sB[b + 2] + (size_t)n0 * 40 + ks * 16, 40);
            wmma::load_matrix_sync(bl1, sB[b + 2] + (size_t)(n0 + 16) * 40 + ks * 16, 40);

            wmma::mma_sync(acc[0][0], ah0, bh0, acc[0][0]);
            wmma::mma_sync(acc[0][1], ah0, bh1, acc[0][1]);
            wmma::mma_sync(acc[1][0], ah1, bh0, acc[1][0]);
            wmma::mma_sync(acc[1][1], ah1, bh1, acc[1][1]);
            wmma::mma_sync(acc[0][0], ah0, bl0, acc[0][0]);
            wmma::mma_sync(acc[0][1], ah0, bl1, acc[0][1]);
            wmma::mma_sync(acc[1][0], ah1, bl0, acc[1][0]);
            wmma::mma_sync(acc[1][1], ah1, bl1, acc[1][1]);
            wmma::mma_sync(acc[0][0], al0, bh0, acc[0][0]);
            wmma::mma_sync(acc[0][1], al0, bh1, acc[0][1]);
            wmma::mma_sync(acc[1][0], al1, bh0, acc[1][0]);
            wmma::mma_sync(acc[1][1], al1, bh1, acc[1][1]);
        }
        __syncthreads();
    }

#pragma unroll
    for (int mi = 0; mi < 2; mi++)
#pragma unroll
        for (int ni = 0; ni < 2; ni++)
            wmma::store_matrix_sync(scratch + (size_t)(n0 + ni * 16) * 132 + m0 + mi * 16,
                                    acc[mi][ni], 132, wmma::mem_col_major);
    __syncthreads();

    const int lane = t & 31;
#pragma unroll
    for (int nn = 0; nn < 8; nn++) {
        int n = (w << 3) + nn;
        float bv = bias[col0 + n];
        float* orow = out + (size_t)b2 * 1048576 + (size_t)(col0 + n) * 4096 + hw0;
#pragma unroll
        for (int it = 0; it < 4; it++) {
            int m = (it << 5) + lane;
            orow[m] = scratch[n * 132 + m] + bv;
        }
    }
}

// ---------------- windowed attention: fp32 in, bf16 h/l out ----------------
__global__ __launch_bounds__(64) void attn_kernel(const float* __restrict__ qkv,
                                                  __nv_bfloat16* __restrict__ Oh,
                                                  __nv_bfloat16* __restrict__ Ol) {
    const int h = blockIdx.x, w = blockIdx.y;
    __shared__ float4 sK[CAP][4];
    __shared__ float4 sV[CAP][4];
    const int t = threadIdx.x;
    const int T = g_win_cnt[w];
    const int* wt = &g_win_tok[w * CAP];
    for (int j = t; j < T; j += 64) {
        int tok = wt[j];
        const float4* kp = (const float4*)(qkv + (size_t)tok * 384 + 128 + h * 16);
        const float4* vp = (const float4*)(qkv + (size_t)tok * 384 + 256 + h * 16);
        sK[j][0] = kp[0]; sK[j][1] = kp[1]; sK[j][2] = kp[2]; sK[j][3] = kp[3];
        sV[j][0] = vp[0]; sV[j][1] = vp[1]; sV[j][2] = vp[2]; sV[j][3] = vp[3];
    }
    __syncthreads();
    int qtok = wt[t];
    const float4* qp = (const float4*)(qkv + (size_t)qtok * 384 + h * 16);
    float4 q0 = qp[0], q1 = qp[1], q2 = qp[2], q3 = qp[3];
    float m = -1e30f, l = 0.f;
    float4 o0 = {0,0,0,0}, o1 = {0,0,0,0}, o2 = {0,0,0,0}, o3 = {0,0,0,0};
    for (int j = 0; j < T; j++) {
        float4 k0 = sK[j][0], k1 = sK[j][1], k2 = sK[j][2], k3 = sK[j][3];
        float s = q0.x*k0.x + q0.y*k0.y + q0.z*k0.z + q0.w*k0.w
                + q1.x*k1.x + q1.y*k1.y + q1.z*k1.z + q1.w*k1.w
                + q2.x*k2.x + q2.y*k2.y + q2.z*k2.z + q2.w*k2.w
                + q3.x*k3.x + q3.y*k3.y + q3.z*k3.z + q3.w*k3.w;
        s *= 0.25f;
        float mn = fmaxf(m, s);
        float sc = __expf(m - mn);
        float p  = __expf(s - mn);
        l = l * sc + p;
        float4 v0 = sV[j][0], v1 = sV[j][1], v2 = sV[j][2], v3 = sV[j][3];
        o0.x = o0.x*sc + p*v0.x; o0.y = o0.y*sc + p*v0.y; o0.z = o0.z*sc + p*v0.z; o0.w = o0.w*sc + p*v0.w;
        o1.x = o1.x*sc + p*v1.x; o1.y = o1.y*sc + p*v1.y; o1.z = o1.z*sc + p*v1.z; o1.w = o1.w*sc + p*v1.w;
        o2.x = o2.x*sc + p*v2.x; o2.y = o2.y*sc + p*v2.y; o2.z = o2.z*sc + p*v2.z; o2.w = o2.w*sc + p*v2.w;
        o3.x = o3.x*sc + p*v3.x; o3.y = o3.y*sc + p*v3.y; o3.z = o3.z*sc + p*v3.z; o3.w = o3.w*sc + p*v3.w;
        m = mn;
    }
    float inv = 1.f / l;
    float ov[16] = { o0.x*inv, o0.y*inv, o0.z*inv, o0.w*inv,
                     o1.x*inv, o1.y*inv, o1.z*inv, o1.w*inv,
                     o2.x*inv, o2.y*inv, o2.z*inv, o2.w*inv,
                     o3.x*inv, o3.y*inv, o3.z*inv, o3.w*inv };
    uint32_t* oh32 = (uint32_t*)Oh;
    uint32_t* ol32 = (uint32_t*)Ol;
    int ob = qtok * 64 + h * 8;
#pragma unroll
    for (int j = 0; j < 8; j++) {
        uint32_t hh = bf16x2_of(ov[2*j+1], ov[2*j]);
        oh32[ob + j] = hh;
        ol32[ob + j] = bf16x2_of(ov[2*j+1] - bf16hi_f(hh), ov[2*j] - bf16lo_f(hh));
    }
}

// ============================================================================
// Fused proj + RK4 ODE (wmma bf16 h/l). 128 CTAs x 256 thr; CTA owns 64 rows.
// SMEM layout:
//   [0)      scratch f32 64x128            32768
//   [32768)  sBias (bode)                    512
//   [33280)  sWh ode 128x136 bf16          34816
//   [68096)  sWl ode                       34816
//   [102912) sZh 64x136 bf16               17408
//   [120320) sZl                           17408
//   [137728) sPWh proj W (-> sImg f32 after proj)  34816
//   [172544) sPWl proj W                   34816   total 207360
// ============================================================================
#define ODE_SMEM 207360

// 3-pass hi/lo 64x128x128 MMA: A(h/l) 64x128 pitch136, B(h/l) 128x128 pitch136
__device__ __forceinline__ void mma3pass(const __nv_bfloat16* Ahs, const __nv_bfloat16* Als,
                                         const __nv_bfloat16* Bhs, const __nv_bfloat16* Bls,
                                         float* scratch, int m0, int n0) {
    wmma::fragment<wmma::accumulator, 16, 16, 16, float> acc[2][2];
#pragma unroll
    for (int mi = 0; mi < 2; mi++)
#pragma unroll
        for (int ni = 0; ni < 2; ni++)
            wmma::fill_fragment(acc[mi][ni], 0.f);
#pragma unroll
    for (int k = 0; k < 8; k++) {
        wmma::fragment<wmma::matrix_a, 16, 16, 16, __nv_bfloat16, wmma::row_major> ah0, ah1, al0, al1;
        wmma::fragment<wmma::matrix_b, 16, 16, 16, __nv_bfloat16, wmma::col_major> bh0, bh1, bl0, bl1;
        wmma::load_matrix_sync(ah0, Ahs + (size_t)m0 * 136 + k * 16, 136);
        wmma::load_matrix_sync(ah1, Ahs + (size_t)(m0 + 16) * 136 + k * 16, 136);
        wmma::load_matrix_sync(al0, Als + (size_t)m0 * 136 + k * 16, 136);
        wmma::load_matrix_sync(al1, Als + (size_t)(m0 + 16) * 136 + k * 16, 136);
        wmma::load_matrix_sync(bh0, Bhs + (size_t)n0 * 136 + k * 16, 136);
        wmma::load_matrix_sync(bh1, Bhs + (size_t)(n0 + 16) * 136 + k * 16, 136);
        wmma::load_matrix_sync(bl0, Bls + (size_t)n0 * 136 + k * 16, 136);
        wmma::load_matrix_sync(bl1, Bls + (size_t)(n0 + 16) * 136 + k * 16, 136);

        wmma::mma_sync(acc[0][0], ah0, bh0, acc[0][0]);
        wmma::mma_sync(acc[0][1], ah0, bh1, acc[0][1]);
        wmma::mma_sync(acc[1][0], ah1, bh0, acc[1][0]);
        wmma::mma_sync(acc[1][1], ah1, bh1, acc[1][1]);
        wmma::mma_sync(acc[0][0], ah0, bl0, acc[0][0]);
        wmma::mma_sync(acc[0][1], ah0, bl1, acc[0][1]);
        wmma::mma_sync(acc[1][0], ah1, bl0, acc[1][0]);
        wmma::mma_sync(acc[1][1], ah1, bl1, acc[1][1]);
        wmma::mma_sync(acc[0][0], al0, bh0, acc[0][0]);
        wmma::mma_sync(acc[0][1], al0, bh1, acc[0][1]);
        wmma::mma_sync(acc[1][0], al1, bh0, acc[1][0]);
        wmma::mma_sync(acc[1][1], al1, bh1, acc[1][1]);
    }
#pragma unroll
    for (int mi = 0; mi < 2; mi++)
#pragma unroll
        for (int ni = 0; ni < 2; ni++)
            wmma::store_matrix_sync(scratch + (size_t)(m0 + mi * 16) * 128 + n0 + ni * 16,
                                    acc[mi][ni], 128, wmma::mem_row_major);
}

__global__ __launch_bounds__(256, 1) void ode_wmma(const __nv_bfloat16* __restrict__ Oh,
                                                   const __nv_bfloat16* __restrict__ Ol,
                                                   const __nv_bfloat16* __restrict__ PWh,
                                                   const __nv_bfloat16* __restrict__ PWl,
                                                   const float* __restrict__ pbias,
                                                   const __nv_bfloat16* __restrict__ Wh_g,
                                                   const __nv_bfloat16* __restrict__ Wl_g,
                                                   const float* __restrict__ bias,
                                                   __nv_bfloat16* __restrict__ Rh,
                                                   __nv_bfloat16* __restrict__ Rl) {
    extern __shared__ __align__(16) char sm[];
    float* scratch = (float*)sm;
    float* sBias   = (float*)(sm + 32768);
    __nv_bfloat16* sWh  = (__nv_bfloat16*)(sm + 33280);
    __nv_bfloat16* sWl  = (__nv_bfloat16*)(sm + 68096);
    __nv_bfloat16* sZh  = (__nv_bfloat16*)(sm + 102912);
    __nv_bfloat16* sZl  = (__nv_bfloat16*)(sm + 120320);
    __nv_bfloat16* sPWh = (__nv_bfloat16*)(sm + 137728);
    __nv_bfloat16* sPWl = (__nv_bfloat16*)(sm + 172544);
    float* sImg = (float*)(sm + 137728);   // reuses proj-W space after proj

    const int t = threadIdx.x;
    const int w = t >> 5;
    const int row0 = blockIdx.x << 6;

    // load ODE W and proj W (pitch 68 u32)
    {
        const uint32_t* wh32 = (const uint32_t*)Wh_g;
        const uint32_t* wl32 = (const uint32_t*)Wl_g;
        const uint32_t* ph32 = (const uint32_t*)PWh;
        const uint32_t* pl32 = (const uint32_t*)PWl;
        uint32_t* sWh32 = (uint32_t*)sWh;
        uint32_t* sWl32 = (uint32_t*)sWl;
        uint32_t* sPh32 = (uint32_t*)sPWh;
        uint32_t* sPl32 = (uint32_t*)sPWl;
        for (int idx = t; idx < 8192; idx += 256) {
            int n = idx >> 6, c2 = idx & 63;
            sWh32[n * 68 + c2] = wh32[idx];
            sWl32[n * 68 + c2] = wl32[idx];
            sPh32[n * 68 + c2] = ph32[idx];
            sPl32[n * 68 + c2] = pl32[idx];
        }
    }
    if (t < 128) sBias[t] = bias[t];
    // load o rows into sZ (A of proj GEMM)
    {
        const uint32_t* oh32 = (const uint32_t*)Oh + (size_t)row0 * 64;
        const uint32_t* ol32 = (const uint32_t*)Ol + (size_t)row0 * 64;
        uint32_t* zh = (uint32_t*)sZh;
        uint32_t* zl = (uint32_t*)sZl;
        for (int idx = t; idx < 4096; idx += 256) {
            int n = idx >> 6, c2 = idx & 63;
            zh[n * 68 + c2] = oh32[idx];
            zl[n * 68 + c2] = ol32[idx];
        }
    }
    __syncthreads();

    const int wm = w >> 2, wn = w & 3;
    const int m0 = wm << 5, n0 = wn << 5;

    // ---- proj GEMM: img = o @ Wpr^T + bpr ----
    mma3pass(sZh, sZl, sPWh, sPWl, scratch, m0, n0);
    __syncthreads();

    const int r = t >> 2, c0 = (t & 3) << 5;
    float y[32], accv[32];
    uint32_t* zh32 = (uint32_t*)(sZh + r * 136 + c0);
    uint32_t* zl32 = (uint32_t*)(sZl + r * 136 + c0);
#pragma unroll
    for (int q = 0; q < 8; q++) {
        float4 v = *(float4*)(scratch + r * 128 + c0 + q * 4);
        float4 bb = *(const float4*)(pbias + c0 + q * 4);
        v.x += bb.x; v.y += bb.y; v.z += bb.z; v.w += bb.w;
        y[q*4] = v.x; y[q*4+1] = v.y; y[q*4+2] = v.z; y[q*4+3] = v.w;
        *(float4*)(sImg + r * 128 + c0 + q * 4) = v;
    }
#pragma unroll
    for (int j = 0; j < 16; j++) {
        float x0 = y[2*j], x1 = y[2*j+1];
        uint32_t h = bf16x2_of(x1, x0);
        zh32[j] = h;
        zl32[j] = bf16x2_of(x1 - bf16hi_f(h), x0 - bf16lo_f(h));
    }
    __syncthreads();

    // ---- 16 RK4 evaluations ----
    for (int ev = 0; ev < 16; ev++) {
        mma3pass(sZh, sZl, sWh, sWl, scratch, m0, n0);
        __syncthreads();

        const int st = ev & 3;
        const float zc = (st < 2) ? 0.125f : 0.25f;
        const float aw = (st == 1 || st == 2) ? 2.f : 1.f;
#pragma unroll
        for (int j = 0; j < 16; j++) {
            float k0f = fmaxf(scratch[r * 128 + c0 + 2*j]     + sBias[c0 + 2*j],     0.f);
            float k1f = fmaxf(scratch[r * 128 + c0 + 2*j + 1] + sBias[c0 + 2*j + 1], 0.f);
            float a0 = (st == 0) ? k0f : accv[2*j]     + aw * k0f;
            float a1 = (st == 0) ? k1f : accv[2*j + 1] + aw * k1f;
            accv[2*j] = a0; accv[2*j+1] = a1;
            float z0, z1;
            if (st < 3) { z0 = y[2*j] + zc * k0f; z1 = y[2*j+1] + zc * k1f; }
            else {
                y[2*j]   += (1.f / 24.f) * a0;
                y[2*j+1] += (1.f / 24.f) * a1;
                z0 = y[2*j]; z1 = y[2*j+1];
            }
            uint32_t h = bf16x2_of(z1, z0);
            zh32[j] = h;
            zl32[j] = bf16x2_of(z1 - bf16hi_f(h), z0 - bf16lo_f(h));
        }
        __syncthreads();
    }

    // ---- res = y_final + img, emit bf16 h/l ----
    uint32_t* rh32 = (uint32_t*)Rh;
    uint32_t* rl32 = (uint32_t*)Rl;
    int ob = (row0 + r) * 64 + (c0 >> 1);
#pragma unroll
    for (int q = 0; q < 8; q++) {
        float4 v = *(const float4*)(sImg + r * 128 + c0 + q * 4);
        float r0 = v.x + y[q*4],   r1 = v.y + y[q*4+1];
        float r2 = v.z + y[q*4+2], r3 = v.w + y[q*4+3];
        uint32_t h01 = bf16x2_of(r1, r0);
        uint32_t h23 = bf16x2_of(r3, r2);
        rh32[ob + q*2]     = h01;
        rh32[ob + q*2 + 1] = h23;
        rl32[ob + q*2]     = bf16x2_of(r1 - bf16hi_f(h01), r0 - bf16lo_f(h01));
        rl32[ob + q*2 + 1] = bf16x2_of(r3 - bf16hi_f(h23), r2 - bf16lo_f(h23));
    }
}

// ---------------- launch ----------------
extern "C" void kernel_launch(void* const* d_in, const int* in_sizes, int n_in,
                              void* d_out, int out_size) {
    const float* img   = (const float*)d_in[0];
    const int*   ptsuv = (const int*)  d_in[1];
    const float* ptsf  = (const float*)d_in[2];
    const float* wci   = (const float*)d_in[3];
    const float* bci   = (const float*)d_in[4];
    const float* wqkv  = (const float*)d_in[5];
    const float* bqkv  = (const float*)d_in[6];
    const float* wpr   = (const float*)d_in[7];
    const float* bpr   = (const float*)d_in[8];
    const float* wode  = (const float*)d_in[9];
    const float* bode  = (const float*)d_in[10];
    const float* wco   = (const float*)d_in[11];
    const float* bco   = (const float*)d_in[12];
    float* out = (float*)d_out;

    float *pqkv;
    __nv_bfloat16 *pwh, *pwl, *pfh, *pfl, *poh, *pol, *prh, *prl;
    cudaGetSymbolAddress((void**)&pqkv, g_qkv);
    cudaGetSymbolAddress((void**)&pwh,  g_wh);
    cudaGetSymbolAddress((void**)&pwl,  g_wl);
    cudaGetSymbolAddress((void**)&pfh,  g_feath);
    cudaGetSymbolAddress((void**)&pfl,  g_featl);
    cudaGetSymbolAddress((void**)&poh,  g_oh);
    cudaGetSymbolAddress((void**)&pol,  g_ol);
    cudaGetSymbolAddress((void**)&prh,  g_resh);
    cudaGetSymbolAddress((void**)&prl,  g_resl);

    cudaFuncSetAttribute(ode_wmma,     cudaFuncAttributeMaxDynamicSharedMemorySize, ODE_SMEM);
    cudaFuncSetAttribute(bfgemm_bf,    cudaFuncAttributeMaxDynamicSharedMemorySize, GBF_SMEM);
    cudaFuncSetAttribute(bfgemm_tr_bf, cudaFuncAttributeMaxDynamicSharedMemorySize, GTR_SMEM);

    // prep: weights + points + wid/hist/pixel slots (merged)
    prep<<<1632, 256>>>(wci, wqkv, wpr, wode, wco, ptsf, ptsuv);
    // scatter with inline scan
    pt_scatter<<<NCHUNK, 256>>>();
    // conv_in from NCHW -> feat h/l
    bfgemm_ca<<<dim3(2, 64), 256>>>(img, pwh + WOFF_CI, pwl + WOFF_CI, bci, pfh, pfl, 128, 256);
    // qkv merged: Q (cols<128) only for pixel rows (by<64)
    bfgemm_bf<<<dim3(6, 128), 256, GBF_SMEM>>>(pfh, pfl, pwh + WOFF_QKV, pwl + WOFF_QKV,
                                               bqkv, pqkv, 384, 128, 128, 64);
    // attention -> o h/l
    attn_kernel<<<dim3(8, 128), 64>>>(pqkv, poh, pol);
    // fused proj + RK4 ODE -> res h/l
    ode_wmma<<<128, 256, ODE_SMEM>>>(poh, pol, pwh + WOFF_PR, pwl + WOFF_PR, bpr,
                                     pwh + WOFF_ODE, pwl + WOFF_ODE, bode, prh, prl);
    // conv_out -> NCHW out
    bfgemm_tr_bf<<<dim3(4, 64), 256, GTR_SMEM>>>(prh, prl, pwh + WOFF_CO, pwl + WOFF_CO,
                                                 bco, out, 128);
}